// round 5
// baseline (speedup 1.0000x reference)
#include <cuda_runtime.h>
#include <math.h>
#include <stdint.h>

#define N_LEVELS 16
#define LOG2_HASHMAP_SIZE 19
#define HASH_MASK ((1u << LOG2_HASHMAP_SIZE) - 1u)
#define N_POINTS 1048576
#define PRIME_Y 2654435761u
#define PRIME_Z 805459861u
#define N_BINS 32768          // 32^3 spatial bins over [0,1]^3

struct Res16 { float r[16]; };

// Scratch (no cudaMalloc allowed): sorted points + orig index packed in .w
__device__ float4       g_xs4[N_POINTS];     // 16 MB
__device__ unsigned int g_hist[N_BINS];      // counts -> offsets -> cursors

__device__ __forceinline__ int bin_key(float px, float py, float pz) {
    int bx = (int)(px * 32.0f); bx = bx < 0 ? 0 : (bx > 31 ? 31 : bx);
    int by = (int)(py * 32.0f); by = by < 0 ? 0 : (by > 31 ? 31 : by);
    int bz = (int)(pz * 32.0f); bz = bz < 0 ? 0 : (bz > 31 ? 31 : bz);
    return (bx << 10) | (by << 5) | bz;
}

__global__ void zero_hist_kernel() {
    int i = blockIdx.x * blockDim.x + threadIdx.x;
    if (i < N_BINS) g_hist[i] = 0u;
}

__global__ void hist_kernel(const float* __restrict__ x) {
    int i = blockIdx.x * blockDim.x + threadIdx.x;
    if (i >= N_POINTS) return;
    float px = __ldg(&x[3 * i]), py = __ldg(&x[3 * i + 1]), pz = __ldg(&x[3 * i + 2]);
    atomicAdd(&g_hist[bin_key(px, py, pz)], 1u);
}

// Single-block exclusive scan over 32768 bins (1024 threads x 32 bins each).
__global__ void scan_kernel() {
    __shared__ unsigned int s[1024];
    int t = threadIdx.x;
    unsigned int local[32];
    unsigned int sum = 0;
#pragma unroll
    for (int i = 0; i < 32; i++) { local[i] = g_hist[t * 32 + i]; sum += local[i]; }
    s[t] = sum;
    __syncthreads();
    for (int off = 1; off < 1024; off <<= 1) {
        unsigned int v = (t >= off) ? s[t - off] : 0u;
        __syncthreads();
        s[t] += v;
        __syncthreads();
    }
    unsigned int run = (t == 0) ? 0u : s[t - 1];
#pragma unroll
    for (int i = 0; i < 32; i++) { g_hist[t * 32 + i] = run; run += local[i]; }
}

__global__ void scatter_kernel(const float* __restrict__ x) {
    int i = blockIdx.x * blockDim.x + threadIdx.x;
    if (i >= N_POINTS) return;
    float px = __ldg(&x[3 * i]), py = __ldg(&x[3 * i + 1]), pz = __ldg(&x[3 * i + 2]);
    unsigned int r = atomicAdd(&g_hist[bin_key(px, py, pz)], 1u);
    g_xs4[r] = make_float4(px, py, pz, __int_as_float(i));
}

// Main: block = 512 threads = 16 warps. Warp w handles level w for 32
// spatially-adjacent (sorted) points -> coarse-level gathers coalesce.
__global__ void __launch_bounds__(512)
hash_embed_kernel(const float* __restrict__ tables,
                  float2* __restrict__ out,
                  Res16 R)
{
    __shared__ float2 s_out[32][17];   // [point][level], padded row
    __shared__ int    s_idx[32];

    const int warp = threadIdx.x >> 5;   // = level
    const int lane = threadIdx.x & 31;   // = point within block
    const int base = blockIdx.x * 32;

    const float4 pv = g_xs4[base + lane];
    const float px = pv.x, py = pv.y, pz = pv.z;
    if (warp == 0) s_idx[lane] = __float_as_int(pv.w);

    const int level = warp;
    const float res  = R.r[level];
    const float grid = 2.0f / res;   // fp32, matches reference

    // bl = floor((x - BOX_MIN)/grid), BOX_MIN = -1. Bit-exact IEEE path.
    const float fx = (px + 1.0f) / grid;
    const float fy = (py + 1.0f) / grid;
    const float fz = (pz + 1.0f) / grid;
    const float bxf = floorf(fx);
    const float byf = floorf(fy);
    const float bzf = floorf(fz);
    const int bx = (int)bxf;
    const int by = (int)byf;
    const int bz = (int)bzf;

    // Weights: mathematically (x - vmin)/(vmax - vmin) == frac(fx); ~1 ulp
    // from the reference formulation, far under the 1e-3 tolerance.
    const float wx = fx - bxf;
    const float wy = fy - byf;
    const float wz = fz - bzf;

    const uint32_t hy0 = (uint32_t)by * PRIME_Y;
    const uint32_t hy1 = (uint32_t)(by + 1) * PRIME_Y;
    const uint32_t hz0 = (uint32_t)bz * PRIME_Z;
    const uint32_t hz1 = (uint32_t)(bz + 1) * PRIME_Z;

    const uint32_t hyz00 = hy0 ^ hz0;
    const uint32_t hyz01 = hy0 ^ hz1;
    const uint32_t hyz10 = hy1 ^ hz0;
    const uint32_t hyz11 = hy1 ^ hz1;

    const float2* __restrict__ tab =
        (const float2*)tables + ((size_t)level << LOG2_HASHMAP_SIZE);
    const float4* __restrict__ tab4 = (const float4*)tab;

    // Corner indices for x = bx (always inside the float4 we fetch, so the
    // wide load costs no extra cache lines for any parity).
    const uint32_t h00 = ((uint32_t)bx ^ hyz00) & HASH_MASK;
    const uint32_t h01 = ((uint32_t)bx ^ hyz01) & HASH_MASK;
    const uint32_t h10 = ((uint32_t)bx ^ hyz10) & HASH_MASK;
    const uint32_t h11 = ((uint32_t)bx ^ hyz11) & HASH_MASK;

    // 4 unconditional aligned float4 loads, MLP=4.
    const float4 q00 = __ldg(&tab4[h00 >> 1]);
    const float4 q01 = __ldg(&tab4[h01 >> 1]);
    const float4 q10 = __ldg(&tab4[h10 >> 1]);
    const float4 q11 = __ldg(&tab4[h11 >> 1]);

    // Entry h is the low or high half of its float4 by parity of h.
    float2 v000 = (h00 & 1u) ? make_float2(q00.z, q00.w) : make_float2(q00.x, q00.y);
    float2 v001 = (h01 & 1u) ? make_float2(q01.z, q01.w) : make_float2(q01.x, q01.y);
    float2 v010 = (h10 & 1u) ? make_float2(q10.z, q10.w) : make_float2(q10.x, q10.y);
    float2 v011 = (h11 & 1u) ? make_float2(q11.z, q11.w) : make_float2(q11.x, q11.y);

    // For even bx: the (bx+1) corner is h^1 = the other half of the same float4.
    float2 v100 = (h00 & 1u) ? make_float2(q00.x, q00.y) : make_float2(q00.z, q00.w);
    float2 v101 = (h01 & 1u) ? make_float2(q01.x, q01.y) : make_float2(q01.z, q01.w);
    float2 v110 = (h10 & 1u) ? make_float2(q10.x, q10.y) : make_float2(q10.z, q10.w);
    float2 v111 = (h11 & 1u) ? make_float2(q11.x, q11.y) : make_float2(q11.z, q11.w);

    // Odd bx: (bx+1) corners need their own gathers. ONE divergent branch,
    // ~half the lanes, 4 independent loads.
    if (bx & 1) {
        const uint32_t g00 = ((uint32_t)(bx + 1) ^ hyz00) & HASH_MASK;
        const uint32_t g01 = ((uint32_t)(bx + 1) ^ hyz01) & HASH_MASK;
        const uint32_t g10 = ((uint32_t)(bx + 1) ^ hyz10) & HASH_MASK;
        const uint32_t g11 = ((uint32_t)(bx + 1) ^ hyz11) & HASH_MASK;
        v100 = __ldg(&tab[g00]);
        v101 = __ldg(&tab[g01]);
        v110 = __ldg(&tab[g10]);
        v111 = __ldg(&tab[g11]);
    }

    const float owx = 1.0f - wx;
    const float owy = 1.0f - wy;
    const float owz = 1.0f - wz;

    float2 c00, c01, c10, c11;
    c00.x = v000.x * owx + v100.x * wx;  c00.y = v000.y * owx + v100.y * wx;
    c01.x = v001.x * owx + v101.x * wx;  c01.y = v001.y * owx + v101.y * wx;
    c10.x = v010.x * owx + v110.x * wx;  c10.y = v010.y * owx + v110.y * wx;
    c11.x = v011.x * owx + v111.x * wx;  c11.y = v011.y * owx + v111.y * wx;

    float2 c0, c1;
    c0.x = c00.x * owy + c10.x * wy;  c0.y = c00.y * owy + c10.y * wy;
    c1.x = c01.x * owy + c11.x * wy;  c1.y = c01.y * owy + c11.y * wy;

    float2 r2;
    r2.x = c0.x * owz + c1.x * wz;
    r2.y = c0.y * owz + c1.y * wz;

    s_out[lane][warp] = r2;
    __syncthreads();

    // Coalesced writeback: 16 consecutive threads emit one point's 128B row.
    const int pt  = threadIdx.x >> 4;
    const int lev = threadIdx.x & 15;
    out[(size_t)s_idx[pt] * N_LEVELS + lev] = s_out[pt][lev];
}

extern "C" void kernel_launch(void* const* d_in, const int* in_sizes, int n_in,
                              void* d_out, int out_size)
{
    const float* x      = (const float*)d_in[0];
    const float* tables = (const float*)d_in[1];
    float2* out         = (float2*)d_out;

    // Replicate numpy's RESOLUTIONS computation exactly (double libm, floor).
    Res16 R;
    const double b = exp((log(512.0) - log(16.0)) / 15.0);
    for (int i = 0; i < 16; i++) {
        R.r[i] = (float)floor(16.0 * pow(b, (double)i));
    }

    zero_hist_kernel<<<N_BINS / 1024, 1024>>>();
    hist_kernel<<<N_POINTS / 256, 256>>>(x);
    scan_kernel<<<1, 1024>>>();
    scatter_kernel<<<N_POINTS / 256, 256>>>(x);
    hash_embed_kernel<<<N_POINTS / 32, 512>>>(tables, out, R);
}

// round 6
// speedup vs baseline: 1.0795x; 1.0795x over previous
#include <cuda_runtime.h>
#include <math.h>
#include <stdint.h>

#define N_LEVELS 16
#define LOG2_HASHMAP_SIZE 19
#define HASH_MASK ((1u << LOG2_HASHMAP_SIZE) - 1u)
#define N_POINTS 1048576
#define PRIME_Y 2654435761u
#define PRIME_Z 805459861u
#define N_BINS 32768          // 32^3 spatial bins over [0,1]^3

struct Res16 { float r[16]; };

// Scratch (no cudaMalloc allowed): sorted points + orig index packed in .w
__device__ float4       g_xs4[N_POINTS];     // 16 MB
__device__ unsigned int g_hist[N_BINS];      // counts -> offsets -> cursors

__device__ __forceinline__ int bin_key(float px, float py, float pz) {
    int bx = (int)(px * 32.0f); bx = bx < 0 ? 0 : (bx > 31 ? 31 : bx);
    int by = (int)(py * 32.0f); by = by < 0 ? 0 : (by > 31 ? 31 : by);
    int bz = (int)(pz * 32.0f); bz = bz < 0 ? 0 : (bz > 31 ? 31 : bz);
    return (bx << 10) | (by << 5) | bz;
}

__global__ void zero_hist_kernel() {
    int i = blockIdx.x * blockDim.x + threadIdx.x;
    if (i < N_BINS) g_hist[i] = 0u;
}

// 4 points per thread via three aligned float4 loads (12 floats = 48B).
__global__ void hist_kernel(const float4* __restrict__ x4) {
    int t = blockIdx.x * blockDim.x + threadIdx.x;
    if (t >= N_POINTS / 4) return;
    const float4 a = __ldg(&x4[3 * t + 0]);
    const float4 b = __ldg(&x4[3 * t + 1]);
    const float4 c = __ldg(&x4[3 * t + 2]);
    atomicAdd(&g_hist[bin_key(a.x, a.y, a.z)], 1u);
    atomicAdd(&g_hist[bin_key(a.w, b.x, b.y)], 1u);
    atomicAdd(&g_hist[bin_key(b.z, b.w, c.x)], 1u);
    atomicAdd(&g_hist[bin_key(c.y, c.z, c.w)], 1u);
}

// Single-block exclusive scan over 32768 bins (1024 threads x 32 bins each).
__global__ void scan_kernel() {
    __shared__ unsigned int s[1024];
    int t = threadIdx.x;
    unsigned int local[32];
    unsigned int sum = 0;
#pragma unroll
    for (int i = 0; i < 32; i++) { local[i] = g_hist[t * 32 + i]; sum += local[i]; }
    s[t] = sum;
    __syncthreads();
    for (int off = 1; off < 1024; off <<= 1) {
        unsigned int v = (t >= off) ? s[t - off] : 0u;
        __syncthreads();
        s[t] += v;
        __syncthreads();
    }
    unsigned int run = (t == 0) ? 0u : s[t - 1];
#pragma unroll
    for (int i = 0; i < 32; i++) { g_hist[t * 32 + i] = run; run += local[i]; }
}

// 4 points per thread, same float4 pattern as hist.
__global__ void scatter_kernel(const float4* __restrict__ x4) {
    int t = blockIdx.x * blockDim.x + threadIdx.x;
    if (t >= N_POINTS / 4) return;
    const float4 a = __ldg(&x4[3 * t + 0]);
    const float4 b = __ldg(&x4[3 * t + 1]);
    const float4 c = __ldg(&x4[3 * t + 2]);
    const int i0 = 4 * t;

    unsigned int r0 = atomicAdd(&g_hist[bin_key(a.x, a.y, a.z)], 1u);
    g_xs4[r0] = make_float4(a.x, a.y, a.z, __int_as_float(i0 + 0));
    unsigned int r1 = atomicAdd(&g_hist[bin_key(a.w, b.x, b.y)], 1u);
    g_xs4[r1] = make_float4(a.w, b.x, b.y, __int_as_float(i0 + 1));
    unsigned int r2 = atomicAdd(&g_hist[bin_key(b.z, b.w, c.x)], 1u);
    g_xs4[r2] = make_float4(b.z, b.w, c.x, __int_as_float(i0 + 2));
    unsigned int r3 = atomicAdd(&g_hist[bin_key(c.y, c.z, c.w)], 1u);
    g_xs4[r3] = make_float4(c.y, c.z, c.w, __int_as_float(i0 + 3));
}

// Main: block = 512 threads = 16 warps. Warp w handles level w for 32
// spatially-adjacent (sorted) points -> coarse-level gathers coalesce.
__global__ void __launch_bounds__(512)
hash_embed_kernel(const float* __restrict__ tables,
                  float2* __restrict__ out,
                  Res16 R)
{
    __shared__ float2 s_out[32][17];   // [point][level], padded row
    __shared__ float  sxx[32], syy[32], szz[32];
    __shared__ int    s_idx[32];

    const int warp = threadIdx.x >> 5;   // = level
    const int lane = threadIdx.x & 31;   // = point within block
    const int base = blockIdx.x * 32;

    // Stage points once (warp 0) instead of 16 redundant global reads.
    if (warp == 0) {
        const float4 pv = g_xs4[base + lane];
        sxx[lane] = pv.x;
        syy[lane] = pv.y;
        szz[lane] = pv.z;
        s_idx[lane] = __float_as_int(pv.w);
    }
    __syncthreads();

    const float px = sxx[lane];
    const float py = syy[lane];
    const float pz = szz[lane];

    const int level = warp;
    const float res  = R.r[level];
    const float grid = 2.0f / res;   // fp32, matches reference

    // bl = floor((x - BOX_MIN)/grid), BOX_MIN = -1. Bit-exact IEEE path.
    const float fx = (px + 1.0f) / grid;
    const float fy = (py + 1.0f) / grid;
    const float fz = (pz + 1.0f) / grid;
    const float bxf = floorf(fx);
    const float byf = floorf(fy);
    const float bzf = floorf(fz);
    const int bx = (int)bxf;
    const int by = (int)byf;
    const int bz = (int)bzf;

    // Reference weight formulation (round-2 proven).
    const float vminx = bxf * grid - 1.0f;
    const float vminy = byf * grid - 1.0f;
    const float vminz = bzf * grid - 1.0f;
    const float wx = (px - vminx) / ((vminx + grid) - vminx);
    const float wy = (py - vminy) / ((vminy + grid) - vminy);
    const float wz = (pz - vminz) / ((vminz + grid) - vminz);

    const uint32_t hx0 = (uint32_t)bx;
    const uint32_t hx1 = (uint32_t)(bx + 1);
    const uint32_t hy0 = (uint32_t)by * PRIME_Y;
    const uint32_t hy1 = (uint32_t)(by + 1) * PRIME_Y;
    const uint32_t hz0 = (uint32_t)bz * PRIME_Z;
    const uint32_t hz1 = (uint32_t)(bz + 1) * PRIME_Z;

    const float2* __restrict__ tab =
        (const float2*)tables + ((size_t)level << LOG2_HASHMAP_SIZE);

    const float2 v000 = __ldg(&tab[(hx0 ^ hy0 ^ hz0) & HASH_MASK]);
    const float2 v001 = __ldg(&tab[(hx0 ^ hy0 ^ hz1) & HASH_MASK]);
    const float2 v010 = __ldg(&tab[(hx0 ^ hy1 ^ hz0) & HASH_MASK]);
    const float2 v011 = __ldg(&tab[(hx0 ^ hy1 ^ hz1) & HASH_MASK]);
    const float2 v100 = __ldg(&tab[(hx1 ^ hy0 ^ hz0) & HASH_MASK]);
    const float2 v101 = __ldg(&tab[(hx1 ^ hy0 ^ hz1) & HASH_MASK]);
    const float2 v110 = __ldg(&tab[(hx1 ^ hy1 ^ hz0) & HASH_MASK]);
    const float2 v111 = __ldg(&tab[(hx1 ^ hy1 ^ hz1) & HASH_MASK]);

    const float owx = 1.0f - wx;
    const float owy = 1.0f - wy;
    const float owz = 1.0f - wz;

    float2 c00, c01, c10, c11;
    c00.x = v000.x * owx + v100.x * wx;  c00.y = v000.y * owx + v100.y * wx;
    c01.x = v001.x * owx + v101.x * wx;  c01.y = v001.y * owx + v101.y * wx;
    c10.x = v010.x * owx + v110.x * wx;  c10.y = v010.y * owx + v110.y * wx;
    c11.x = v011.x * owx + v111.x * wx;  c11.y = v011.y * owx + v111.y * wx;

    float2 c0, c1;
    c0.x = c00.x * owy + c10.x * wy;  c0.y = c00.y * owy + c10.y * wy;
    c1.x = c01.x * owy + c11.x * wy;  c1.y = c01.y * owy + c11.y * wy;

    float2 r2;
    r2.x = c0.x * owz + c1.x * wz;
    r2.y = c0.y * owz + c1.y * wz;

    s_out[lane][warp] = r2;
    __syncthreads();

    // Coalesced writeback: 16 consecutive threads emit one point's 128B row.
    const int pt  = threadIdx.x >> 4;
    const int lev = threadIdx.x & 15;
    out[(size_t)s_idx[pt] * N_LEVELS + lev] = s_out[pt][lev];
}

extern "C" void kernel_launch(void* const* d_in, const int* in_sizes, int n_in,
                              void* d_out, int out_size)
{
    const float* x      = (const float*)d_in[0];
    const float* tables = (const float*)d_in[1];
    float2* out         = (float2*)d_out;

    // Replicate numpy's RESOLUTIONS computation exactly (double libm, floor).
    Res16 R;
    const double b = exp((log(512.0) - log(16.0)) / 15.0);
    for (int i = 0; i < 16; i++) {
        R.r[i] = (float)floor(16.0 * pow(b, (double)i));
    }

    zero_hist_kernel<<<N_BINS / 1024, 1024>>>();
    hist_kernel<<<(N_POINTS / 4) / 256, 256>>>((const float4*)x);
    scan_kernel<<<1, 1024>>>();
    scatter_kernel<<<(N_POINTS / 4) / 256, 256>>>((const float4*)x);
    hash_embed_kernel<<<N_POINTS / 32, 512>>>(tables, out, R);
}

// round 7
// speedup vs baseline: 1.3569x; 1.2570x over previous
#include <cuda_runtime.h>
#include <math.h>
#include <stdint.h>

#define N_LEVELS 16
#define LOG2_HASHMAP_SIZE 19
#define HASH_MASK ((1u << LOG2_HASHMAP_SIZE) - 1u)
#define N_POINTS 1048576
#define PRIME_Y 2654435761u
#define PRIME_Z 805459861u
#define N_BINS 262144         // 64^3 spatial bins, Morton-ordered

struct Res16 { float r[16]; };

// Scratch (no cudaMalloc allowed)
__device__ float4       g_xs4[N_POINTS];   // sorted points + orig idx in .w
__device__ unsigned int g_hist[N_BINS];    // counts -> offsets -> cursors
__device__ unsigned int g_bsum[256];       // per-scan-block totals

__device__ __forceinline__ uint32_t part1by2(uint32_t v) {
    v &= 0x3FFu;
    v = (v * 0x00010001u) & 0xFF0000FFu;
    v = (v * 0x00000101u) & 0x0F00F00Fu;
    v = (v * 0x00000011u) & 0xC30C30C3u;
    v = (v * 0x00000005u) & 0x49249249u;
    return v;
}

// Morton key over 64^3: consecutive bins tile space as nested cubes, so 32
// consecutive sorted points keep the cubic ~(1/32)^3 warp footprint.
__device__ __forceinline__ int bin_key(float px, float py, float pz) {
    int bx = (int)(px * 64.0f); bx = bx < 0 ? 0 : (bx > 63 ? 63 : bx);
    int by = (int)(py * 64.0f); by = by < 0 ? 0 : (by > 63 ? 63 : by);
    int bz = (int)(pz * 64.0f); bz = bz < 0 ? 0 : (bz > 63 ? 63 : bz);
    return (int)(part1by2((uint32_t)bx)
               | (part1by2((uint32_t)by) << 1)
               | (part1by2((uint32_t)bz) << 2));
}

__global__ void zero_hist_kernel() {
    int i = blockIdx.x * blockDim.x + threadIdx.x;
    g_hist[i] = 0u;
}

__global__ void hist_kernel(const float* __restrict__ x) {
    int i = blockIdx.x * blockDim.x + threadIdx.x;
    if (i >= N_POINTS) return;
    float px = __ldg(&x[3 * i]), py = __ldg(&x[3 * i + 1]), pz = __ldg(&x[3 * i + 2]);
    atomicAdd(&g_hist[bin_key(px, py, pz)], 1u);
}

// Hierarchical exclusive scan over 262144 bins.
// Stage 1: 256 blocks x 1024 threads, exclusive scan within block.
__global__ void scan_local_kernel() {
    __shared__ unsigned int s[1024];
    const int t = threadIdx.x;
    const int gid = blockIdx.x * 1024 + t;
    const unsigned int c = g_hist[gid];
    s[t] = c;
    __syncthreads();
    for (int off = 1; off < 1024; off <<= 1) {
        unsigned int v = (t >= off) ? s[t - off] : 0u;
        __syncthreads();
        s[t] += v;
        __syncthreads();
    }
    g_hist[gid] = s[t] - c;                     // exclusive within block
    if (t == 1023) g_bsum[blockIdx.x] = s[t];   // block total
}

// Stage 2: exclusive scan of the 256 block totals (one block).
__global__ void scan_block_kernel() {
    __shared__ unsigned int s[256];
    const int t = threadIdx.x;
    const unsigned int c = g_bsum[t];
    s[t] = c;
    __syncthreads();
    for (int off = 1; off < 256; off <<= 1) {
        unsigned int v = (t >= off) ? s[t - off] : 0u;
        __syncthreads();
        s[t] += v;
        __syncthreads();
    }
    g_bsum[t] = s[t] - c;
}

// Stage 3: add block offsets.
__global__ void scan_add_kernel() {
    const int gid = blockIdx.x * 1024 + threadIdx.x;
    g_hist[gid] += g_bsum[blockIdx.x];
}

__global__ void scatter_kernel(const float* __restrict__ x) {
    int i = blockIdx.x * blockDim.x + threadIdx.x;
    if (i >= N_POINTS) return;
    float px = __ldg(&x[3 * i]), py = __ldg(&x[3 * i + 1]), pz = __ldg(&x[3 * i + 2]);
    unsigned int r = atomicAdd(&g_hist[bin_key(px, py, pz)], 1u);
    g_xs4[r] = make_float4(px, py, pz, __int_as_float(i));
}

// Main: block = 512 threads = 16 warps. Warp w handles level w for 32
// spatially-adjacent (sorted) points. Byte-for-byte the round-2 kernel.
__global__ void __launch_bounds__(512)
hash_embed_kernel(const float* __restrict__ tables,
                  float2* __restrict__ out,
                  Res16 R)
{
    __shared__ float2 s_out[32][17];   // [point][level], padded row
    __shared__ int    s_idx[32];

    const int warp = threadIdx.x >> 5;   // = level
    const int lane = threadIdx.x & 31;   // = point within block
    const int base = blockIdx.x * 32;

    const float4 pv = g_xs4[base + lane];
    const float px = pv.x, py = pv.y, pz = pv.z;
    if (warp == 0) s_idx[lane] = __float_as_int(pv.w);

    const int level = warp;
    const float res  = R.r[level];
    const float grid = 2.0f / res;   // fp32, matches reference

    // bl = floor((x - BOX_MIN)/grid), BOX_MIN = -1. Bit-exact IEEE path.
    const float fx = (px + 1.0f) / grid;
    const float fy = (py + 1.0f) / grid;
    const float fz = (pz + 1.0f) / grid;
    const float bxf = floorf(fx);
    const float byf = floorf(fy);
    const float bzf = floorf(fz);
    const int bx = (int)bxf;
    const int by = (int)byf;
    const int bz = (int)bzf;

    const float vminx = bxf * grid - 1.0f;
    const float vminy = byf * grid - 1.0f;
    const float vminz = bzf * grid - 1.0f;
    const float wx = (px - vminx) / ((vminx + grid) - vminx);
    const float wy = (py - vminy) / ((vminy + grid) - vminy);
    const float wz = (pz - vminz) / ((vminz + grid) - vminz);

    const uint32_t hx0 = (uint32_t)bx;
    const uint32_t hx1 = (uint32_t)(bx + 1);
    const uint32_t hy0 = (uint32_t)by * PRIME_Y;
    const uint32_t hy1 = (uint32_t)(by + 1) * PRIME_Y;
    const uint32_t hz0 = (uint32_t)bz * PRIME_Z;
    const uint32_t hz1 = (uint32_t)(bz + 1) * PRIME_Z;

    const float2* __restrict__ tab =
        (const float2*)tables + ((size_t)level << LOG2_HASHMAP_SIZE);

    const float2 v000 = __ldg(&tab[(hx0 ^ hy0 ^ hz0) & HASH_MASK]);
    const float2 v001 = __ldg(&tab[(hx0 ^ hy0 ^ hz1) & HASH_MASK]);
    const float2 v010 = __ldg(&tab[(hx0 ^ hy1 ^ hz0) & HASH_MASK]);
    const float2 v011 = __ldg(&tab[(hx0 ^ hy1 ^ hz1) & HASH_MASK]);
    const float2 v100 = __ldg(&tab[(hx1 ^ hy0 ^ hz0) & HASH_MASK]);
    const float2 v101 = __ldg(&tab[(hx1 ^ hy0 ^ hz1) & HASH_MASK]);
    const float2 v110 = __ldg(&tab[(hx1 ^ hy1 ^ hz0) & HASH_MASK]);
    const float2 v111 = __ldg(&tab[(hx1 ^ hy1 ^ hz1) & HASH_MASK]);

    const float owx = 1.0f - wx;
    const float owy = 1.0f - wy;
    const float owz = 1.0f - wz;

    float2 c00, c01, c10, c11;
    c00.x = v000.x * owx + v100.x * wx;  c00.y = v000.y * owx + v100.y * wx;
    c01.x = v001.x * owx + v101.x * wx;  c01.y = v001.y * owx + v101.y * wx;
    c10.x = v010.x * owx + v110.x * wx;  c10.y = v010.y * owx + v110.y * wx;
    c11.x = v011.x * owx + v111.x * wx;  c11.y = v011.y * owx + v111.y * wx;

    float2 c0, c1;
    c0.x = c00.x * owy + c10.x * wy;  c0.y = c00.y * owy + c10.y * wy;
    c1.x = c01.x * owy + c11.x * wy;  c1.y = c01.y * owy + c11.y * wy;

    float2 r2;
    r2.x = c0.x * owz + c1.x * wz;
    r2.y = c0.y * owz + c1.y * wz;

    s_out[lane][warp] = r2;
    __syncthreads();

    // Coalesced writeback: 16 consecutive threads emit one point's 128B row.
    const int pt  = threadIdx.x >> 4;
    const int lev = threadIdx.x & 15;
    out[(size_t)s_idx[pt] * N_LEVELS + lev] = s_out[pt][lev];
}

extern "C" void kernel_launch(void* const* d_in, const int* in_sizes, int n_in,
                              void* d_out, int out_size)
{
    const float* x      = (const float*)d_in[0];
    const float* tables = (const float*)d_in[1];
    float2* out         = (float2*)d_out;

    // Replicate numpy's RESOLUTIONS computation exactly (double libm, floor).
    Res16 R;
    const double b = exp((log(512.0) - log(16.0)) / 15.0);
    for (int i = 0; i < 16; i++) {
        R.r[i] = (float)floor(16.0 * pow(b, (double)i));
    }

    zero_hist_kernel<<<N_BINS / 1024, 1024>>>();
    hist_kernel<<<N_POINTS / 256, 256>>>(x);
    scan_local_kernel<<<256, 1024>>>();
    scan_block_kernel<<<1, 256>>>();
    scan_add_kernel<<<256, 1024>>>();
    scatter_kernel<<<N_POINTS / 256, 256>>>(x);
    hash_embed_kernel<<<N_POINTS / 32, 512>>>(tables, out, R);
}

// round 8
// speedup vs baseline: 1.3617x; 1.0035x over previous
#include <cuda_runtime.h>
#include <math.h>
#include <stdint.h>

#define N_LEVELS 16
#define LOG2_HASHMAP_SIZE 19
#define HASH_MASK ((1u << LOG2_HASHMAP_SIZE) - 1u)
#define N_POINTS 1048576
#define PRIME_Y 2654435761u
#define PRIME_Z 805459861u
#define N_BINS 262144         // 64^3 spatial bins, Morton-ordered

struct Res16 { float r[16]; };

// Scratch (no cudaMalloc allowed)
__device__ float4       g_xs4[N_POINTS];   // sorted points + orig idx in .w
__device__ unsigned int g_hist[N_BINS];    // counts -> offsets -> cursors
__device__ unsigned int g_bsum[256];       // per-scan-block totals

__device__ __forceinline__ uint32_t part1by2(uint32_t v) {
    v &= 0x3FFu;
    v = (v * 0x00010001u) & 0xFF0000FFu;
    v = (v * 0x00000101u) & 0x0F00F00Fu;
    v = (v * 0x00000011u) & 0xC30C30C3u;
    v = (v * 0x00000005u) & 0x49249249u;
    return v;
}

// Morton key over 64^3: consecutive bins tile space as nested cubes, so 32
// consecutive sorted points keep a compact cubic warp footprint.
__device__ __forceinline__ int bin_key(float px, float py, float pz) {
    int bx = (int)(px * 64.0f); bx = bx < 0 ? 0 : (bx > 63 ? 63 : bx);
    int by = (int)(py * 64.0f); by = by < 0 ? 0 : (by > 63 ? 63 : by);
    int bz = (int)(pz * 64.0f); bz = bz < 0 ? 0 : (bz > 63 ? 63 : bz);
    return (int)(part1by2((uint32_t)bx)
               | (part1by2((uint32_t)by) << 1)
               | (part1by2((uint32_t)bz) << 2));
}

__global__ void zero_hist_kernel() {
    int i = blockIdx.x * blockDim.x + threadIdx.x;
    ((uint4*)g_hist)[i] = make_uint4(0u, 0u, 0u, 0u);
}

__global__ void hist_kernel(const float* __restrict__ x) {
    int i = blockIdx.x * blockDim.x + threadIdx.x;
    if (i >= N_POINTS) return;
    float px = __ldg(&x[3 * i]), py = __ldg(&x[3 * i + 1]), pz = __ldg(&x[3 * i + 2]);
    atomicAdd(&g_hist[bin_key(px, py, pz)], 1u);
}

// Hierarchical exclusive scan over 262144 bins.
// Stage 1: 256 blocks x 1024 threads, exclusive scan within block.
__global__ void scan_local_kernel() {
    __shared__ unsigned int s[1024];
    const int t = threadIdx.x;
    const int gid = blockIdx.x * 1024 + t;
    const unsigned int c = g_hist[gid];
    s[t] = c;
    __syncthreads();
    for (int off = 1; off < 1024; off <<= 1) {
        unsigned int v = (t >= off) ? s[t - off] : 0u;
        __syncthreads();
        s[t] += v;
        __syncthreads();
    }
    g_hist[gid] = s[t] - c;                     // exclusive within block
    if (t == 1023) g_bsum[blockIdx.x] = s[t];   // block total
}

// Stage 2 (fused): each block computes its own offset = sum of block totals
// below it (masked reduction over 256 values), then adds it to its 1024 bins.
__global__ void scan_add_kernel() {
    __shared__ unsigned int s[32];
    const int t = threadIdx.x;

    // Masked reduce: sum of g_bsum[b] for b < blockIdx.x, using first 256 lanes.
    unsigned int v = (t < 256 && t < blockIdx.x) ? g_bsum[t] : 0u;
#pragma unroll
    for (int off = 16; off > 0; off >>= 1)
        v += __shfl_down_sync(0xFFFFFFFFu, v, off);
    if ((t & 31) == 0) s[t >> 5] = v;
    __syncthreads();
    if (t == 0) {
        unsigned int acc = 0;
#pragma unroll
        for (int w = 0; w < 32; w++) acc += s[w];
        s[0] = acc;
    }
    __syncthreads();
    const unsigned int offset = s[0];

    const int gid = blockIdx.x * 1024 + t;
    g_hist[gid] += offset;
}

__global__ void scatter_kernel(const float* __restrict__ x) {
    int i = blockIdx.x * blockDim.x + threadIdx.x;
    if (i >= N_POINTS) return;
    float px = __ldg(&x[3 * i]), py = __ldg(&x[3 * i + 1]), pz = __ldg(&x[3 * i + 2]);
    unsigned int r = atomicAdd(&g_hist[bin_key(px, py, pz)], 1u);
    g_xs4[r] = make_float4(px, py, pz, __int_as_float(i));
}

// Main: block = 512 threads = 16 warps. Warp w handles level w for 32
// spatially-adjacent (Morton-sorted) points. PROTECTED: round-2/7 structure.
__global__ void __launch_bounds__(512)
hash_embed_kernel(const float* __restrict__ tables,
                  float2* __restrict__ out,
                  Res16 R)
{
    __shared__ float2 s_out[32][17];   // [point][level], padded row
    __shared__ int    s_idx[32];

    const int warp = threadIdx.x >> 5;   // = level
    const int lane = threadIdx.x & 31;   // = point within block
    const int base = blockIdx.x * 32;

    const float4 pv = g_xs4[base + lane];
    const float px = pv.x, py = pv.y, pz = pv.z;
    if (warp == 0) s_idx[lane] = __float_as_int(pv.w);

    const int level = warp;
    const float res  = R.r[level];
    const float grid = 2.0f / res;   // fp32, matches reference

    // bl = floor((x - BOX_MIN)/grid), BOX_MIN = -1. Bit-exact IEEE path.
    const float fx = (px + 1.0f) / grid;
    const float fy = (py + 1.0f) / grid;
    const float fz = (pz + 1.0f) / grid;
    const float bxf = floorf(fx);
    const float byf = floorf(fy);
    const float bzf = floorf(fz);
    const int bx = (int)bxf;
    const int by = (int)byf;
    const int bz = (int)bzf;

    const float vminx = bxf * grid - 1.0f;
    const float vminy = byf * grid - 1.0f;
    const float vminz = bzf * grid - 1.0f;
    const float wx = (px - vminx) / ((vminx + grid) - vminx);
    const float wy = (py - vminy) / ((vminy + grid) - vminy);
    const float wz = (pz - vminz) / ((vminz + grid) - vminz);

    const uint32_t hx0 = (uint32_t)bx;
    const uint32_t hx1 = (uint32_t)(bx + 1);
    const uint32_t hy0 = (uint32_t)by * PRIME_Y;
    const uint32_t hy1 = (uint32_t)(by + 1) * PRIME_Y;
    const uint32_t hz0 = (uint32_t)bz * PRIME_Z;
    const uint32_t hz1 = (uint32_t)(bz + 1) * PRIME_Z;

    const float2* __restrict__ tab =
        (const float2*)tables + ((size_t)level << LOG2_HASHMAP_SIZE);

    const float2 v000 = __ldg(&tab[(hx0 ^ hy0 ^ hz0) & HASH_MASK]);
    const float2 v001 = __ldg(&tab[(hx0 ^ hy0 ^ hz1) & HASH_MASK]);
    const float2 v010 = __ldg(&tab[(hx0 ^ hy1 ^ hz0) & HASH_MASK]);
    const float2 v011 = __ldg(&tab[(hx0 ^ hy1 ^ hz1) & HASH_MASK]);
    const float2 v100 = __ldg(&tab[(hx1 ^ hy0 ^ hz0) & HASH_MASK]);
    const float2 v101 = __ldg(&tab[(hx1 ^ hy0 ^ hz1) & HASH_MASK]);
    const float2 v110 = __ldg(&tab[(hx1 ^ hy1 ^ hz0) & HASH_MASK]);
    const float2 v111 = __ldg(&tab[(hx1 ^ hy1 ^ hz1) & HASH_MASK]);

    const float owx = 1.0f - wx;
    const float owy = 1.0f - wy;
    const float owz = 1.0f - wz;

    float2 c00, c01, c10, c11;
    c00.x = v000.x * owx + v100.x * wx;  c00.y = v000.y * owx + v100.y * wx;
    c01.x = v001.x * owx + v101.x * wx;  c01.y = v001.y * owx + v101.y * wx;
    c10.x = v010.x * owx + v110.x * wx;  c10.y = v010.y * owx + v110.y * wx;
    c11.x = v011.x * owx + v111.x * wx;  c11.y = v011.y * owx + v111.y * wx;

    float2 c0, c1;
    c0.x = c00.x * owy + c10.x * wy;  c0.y = c00.y * owy + c10.y * wy;
    c1.x = c01.x * owy + c11.x * wy;  c1.y = c01.y * owy + c11.y * wy;

    float2 r2;
    r2.x = c0.x * owz + c1.x * wz;
    r2.y = c0.y * owz + c1.y * wz;

    s_out[lane][warp] = r2;
    __syncthreads();

    // Coalesced writeback: 16 consecutive threads emit one point's 128B row.
    const int pt  = threadIdx.x >> 4;
    const int lev = threadIdx.x & 15;
    out[(size_t)s_idx[pt] * N_LEVELS + lev] = s_out[pt][lev];
}

extern "C" void kernel_launch(void* const* d_in, const int* in_sizes, int n_in,
                              void* d_out, int out_size)
{
    const float* x      = (const float*)d_in[0];
    const float* tables = (const float*)d_in[1];
    float2* out         = (float2*)d_out;

    // Replicate numpy's RESOLUTIONS computation exactly (double libm, floor).
    Res16 R;
    const double b = exp((log(512.0) - log(16.0)) / 15.0);
    for (int i = 0; i < 16; i++) {
        R.r[i] = (float)floor(16.0 * pow(b, (double)i));
    }

    zero_hist_kernel<<<(N_BINS / 4) / 256, 256>>>();
    hist_kernel<<<N_POINTS / 256, 256>>>(x);
    scan_local_kernel<<<256, 1024>>>();
    scan_add_kernel<<<256, 1024>>>();
    scatter_kernel<<<N_POINTS / 256, 256>>>(x);
    hash_embed_kernel<<<N_POINTS / 32, 512>>>(tables, out, R);
}

// round 9
// speedup vs baseline: 1.3847x; 1.0169x over previous
#include <cuda_runtime.h>
#include <math.h>
#include <stdint.h>

#define N_LEVELS 16
#define LOG2_HASHMAP_SIZE 19
#define HASH_MASK ((1u << LOG2_HASHMAP_SIZE) - 1u)
#define N_POINTS 1048576
#define PRIME_Y 2654435761u
#define PRIME_Z 805459861u
#define N_BINS 262144         // 64^3 spatial bins, Morton-ordered

struct Res16 { float r[16]; };

// Scratch (no cudaMalloc allowed)
__device__ float4       g_xs4[N_POINTS];   // sorted points + orig idx in .w
__device__ unsigned int g_hist[N_BINS];    // counts -> offsets -> cursors
__device__ unsigned int g_counter;         // global ticket for block offsets

__device__ __forceinline__ uint32_t part1by2(uint32_t v) {
    v &= 0x3FFu;
    v = (v * 0x00010001u) & 0xFF0000FFu;
    v = (v * 0x00000101u) & 0x0F00F00Fu;
    v = (v * 0x00000011u) & 0xC30C30C3u;
    v = (v * 0x00000005u) & 0x49249249u;
    return v;
}

// Morton key over 64^3: consecutive bins tile space as nested cubes, so 32
// consecutive sorted points keep a compact cubic warp footprint.
__device__ __forceinline__ int bin_key(float px, float py, float pz) {
    int bx = (int)(px * 64.0f); bx = bx < 0 ? 0 : (bx > 63 ? 63 : bx);
    int by = (int)(py * 64.0f); by = by < 0 ? 0 : (by > 63 ? 63 : by);
    int bz = (int)(pz * 64.0f); bz = bz < 0 ? 0 : (bz > 63 ? 63 : bz);
    return (int)(part1by2((uint32_t)bx)
               | (part1by2((uint32_t)by) << 1)
               | (part1by2((uint32_t)bz) << 2));
}

__global__ void zero_hist_kernel() {
    int i = blockIdx.x * blockDim.x + threadIdx.x;
    ((uint4*)g_hist)[i] = make_uint4(0u, 0u, 0u, 0u);
    if (i == 0) g_counter = 0u;
}

__global__ void hist_kernel(const float* __restrict__ x) {
    int i = blockIdx.x * blockDim.x + threadIdx.x;
    if (i >= N_POINTS) return;
    float px = __ldg(&x[3 * i]), py = __ldg(&x[3 * i + 1]), pz = __ldg(&x[3 * i + 2]);
    atomicAdd(&g_hist[bin_key(px, py, pz)], 1u);
}

// Single scan pass: shuffle-based exclusive scan of 1024 bins per block,
// block offset claimed via atomic ticket (chunk permutation is harmless:
// within-chunk Morton order is preserved, output indexed by original id).
__global__ void scan_kernel() {
    __shared__ unsigned int warp_sums[32];
    __shared__ unsigned int s_off;

    const int t    = threadIdx.x;
    const int lanei = t & 31;
    const int wid  = t >> 5;
    const int gid  = blockIdx.x * 1024 + t;

    const unsigned int c = g_hist[gid];

    // Warp-level inclusive scan.
    unsigned int v = c;
#pragma unroll
    for (int off = 1; off < 32; off <<= 1) {
        unsigned int n = __shfl_up_sync(0xFFFFFFFFu, v, off);
        if (lanei >= off) v += n;
    }
    if (lanei == 31) warp_sums[wid] = v;
    __syncthreads();

    // Warp 0 scans the 32 warp totals; lane 31 claims the block ticket.
    if (wid == 0) {
        unsigned int w = warp_sums[lanei];
        unsigned int wv = w;
#pragma unroll
        for (int off = 1; off < 32; off <<= 1) {
            unsigned int n = __shfl_up_sync(0xFFFFFFFFu, wv, off);
            if (lanei >= off) wv += n;
        }
        warp_sums[lanei] = wv - w;            // exclusive warp offset
        if (lanei == 31) s_off = atomicAdd(&g_counter, wv);  // wv = block total
    }
    __syncthreads();

    g_hist[gid] = (v - c) + warp_sums[wid] + s_off;   // global exclusive offset
}

__global__ void scatter_kernel(const float* __restrict__ x) {
    int i = blockIdx.x * blockDim.x + threadIdx.x;
    if (i >= N_POINTS) return;
    float px = __ldg(&x[3 * i]), py = __ldg(&x[3 * i + 1]), pz = __ldg(&x[3 * i + 2]);
    unsigned int r = atomicAdd(&g_hist[bin_key(px, py, pz)], 1u);
    g_xs4[r] = make_float4(px, py, pz, __int_as_float(i));
}

// Main: block = 512 threads = 16 warps. Warp w handles level w for 32
// spatially-adjacent (Morton-sorted) points. PROTECTED: round-2/7 structure.
__global__ void __launch_bounds__(512)
hash_embed_kernel(const float* __restrict__ tables,
                  float2* __restrict__ out,
                  Res16 R)
{
    __shared__ float2 s_out[32][17];   // [point][level], padded row
    __shared__ int    s_idx[32];

    const int warp = threadIdx.x >> 5;   // = level
    const int lane = threadIdx.x & 31;   // = point within block
    const int base = blockIdx.x * 32;

    const float4 pv = g_xs4[base + lane];
    const float px = pv.x, py = pv.y, pz = pv.z;
    if (warp == 0) s_idx[lane] = __float_as_int(pv.w);

    const int level = warp;
    const float res  = R.r[level];
    const float grid = 2.0f / res;   // fp32, matches reference

    // bl = floor((x - BOX_MIN)/grid), BOX_MIN = -1. Bit-exact IEEE path.
    const float fx = (px + 1.0f) / grid;
    const float fy = (py + 1.0f) / grid;
    const float fz = (pz + 1.0f) / grid;
    const float bxf = floorf(fx);
    const float byf = floorf(fy);
    const float bzf = floorf(fz);
    const int bx = (int)bxf;
    const int by = (int)byf;
    const int bz = (int)bzf;

    const float vminx = bxf * grid - 1.0f;
    const float vminy = byf * grid - 1.0f;
    const float vminz = bzf * grid - 1.0f;
    const float wx = (px - vminx) / ((vminx + grid) - vminx);
    const float wy = (py - vminy) / ((vminy + grid) - vminy);
    const float wz = (pz - vminz) / ((vminz + grid) - vminz);

    const uint32_t hx0 = (uint32_t)bx;
    const uint32_t hx1 = (uint32_t)(bx + 1);
    const uint32_t hy0 = (uint32_t)by * PRIME_Y;
    const uint32_t hy1 = (uint32_t)(by + 1) * PRIME_Y;
    const uint32_t hz0 = (uint32_t)bz * PRIME_Z;
    const uint32_t hz1 = (uint32_t)(bz + 1) * PRIME_Z;

    const float2* __restrict__ tab =
        (const float2*)tables + ((size_t)level << LOG2_HASHMAP_SIZE);

    const float2 v000 = __ldg(&tab[(hx0 ^ hy0 ^ hz0) & HASH_MASK]);
    const float2 v001 = __ldg(&tab[(hx0 ^ hy0 ^ hz1) & HASH_MASK]);
    const float2 v010 = __ldg(&tab[(hx0 ^ hy1 ^ hz0) & HASH_MASK]);
    const float2 v011 = __ldg(&tab[(hx0 ^ hy1 ^ hz1) & HASH_MASK]);
    const float2 v100 = __ldg(&tab[(hx1 ^ hy0 ^ hz0) & HASH_MASK]);
    const float2 v101 = __ldg(&tab[(hx1 ^ hy0 ^ hz1) & HASH_MASK]);
    const float2 v110 = __ldg(&tab[(hx1 ^ hy1 ^ hz0) & HASH_MASK]);
    const float2 v111 = __ldg(&tab[(hx1 ^ hy1 ^ hz1) & HASH_MASK]);

    const float owx = 1.0f - wx;
    const float owy = 1.0f - wy;
    const float owz = 1.0f - wz;

    float2 c00, c01, c10, c11;
    c00.x = v000.x * owx + v100.x * wx;  c00.y = v000.y * owx + v100.y * wx;
    c01.x = v001.x * owx + v101.x * wx;  c01.y = v001.y * owx + v101.y * wx;
    c10.x = v010.x * owx + v110.x * wx;  c10.y = v010.y * owx + v110.y * wx;
    c11.x = v011.x * owx + v111.x * wx;  c11.y = v011.y * owx + v111.y * wx;

    float2 c0, c1;
    c0.x = c00.x * owy + c10.x * wy;  c0.y = c00.y * owy + c10.y * wy;
    c1.x = c01.x * owy + c11.x * wy;  c1.y = c01.y * owy + c11.y * wy;

    float2 r2;
    r2.x = c0.x * owz + c1.x * wz;
    r2.y = c0.y * owz + c1.y * wz;

    s_out[lane][warp] = r2;
    __syncthreads();

    // Coalesced writeback: 16 consecutive threads emit one point's 128B row.
    const int pt  = threadIdx.x >> 4;
    const int lev = threadIdx.x & 15;
    out[(size_t)s_idx[pt] * N_LEVELS + lev] = s_out[pt][lev];
}

extern "C" void kernel_launch(void* const* d_in, const int* in_sizes, int n_in,
                              void* d_out, int out_size)
{
    const float* x      = (const float*)d_in[0];
    const float* tables = (const float*)d_in[1];
    float2* out         = (float2*)d_out;

    // Replicate numpy's RESOLUTIONS computation exactly (double libm, floor).
    Res16 R;
    const double b = exp((log(512.0) - log(16.0)) / 15.0);
    for (int i = 0; i < 16; i++) {
        R.r[i] = (float)floor(16.0 * pow(b, (double)i));
    }

    zero_hist_kernel<<<(N_BINS / 4) / 256, 256>>>();
    hist_kernel<<<N_POINTS / 256, 256>>>(x);
    scan_kernel<<<256, 1024>>>();
    scatter_kernel<<<N_POINTS / 256, 256>>>(x);
    hash_embed_kernel<<<N_POINTS / 32, 512>>>(tables, out, R);
}